// round 4
// baseline (speedup 1.0000x reference)
#include <cuda_runtime.h>
#include <cuda_bf16.h>
#include <math.h>

// ---------------------------------------------------------------------------
// B=8; input [8,3,256,256]; segmap [8,19,256,256]
// L1: reflect-pad conv 3->32, 256x256, IN, lrelu       (scalar)
// L2: conv s2 p1 32->64, 128x128, IN, lrelu            (tf32 mma)
// L3: conv s2 p1 64->128, 64x64, IN, lrelu             (tf32 mma)
// L4: convT s2 p1 op1 128->256, 128x128, IN, lrelu     (tf32 mma per parity class)
// L5: reflect-pad conv 256->512, 128x128, tanh         (tf32 mma, 2-wide tile)
// pool: nearest one-hot segmap -> region means -> out [8,19,512]
// ---------------------------------------------------------------------------

#define NB 8
#define NS 19

__device__ float g_act1[NB * 32 * 256 * 256];
__device__ float g_act2[NB * 64 * 128 * 128];
__device__ float g_act3[NB * 128 * 64 * 64];
__device__ float g_act4[NB * 256 * 128 * 128];
__device__ float g_codes[(size_t)NB * 512 * 128 * 128];
__device__ int   g_label[NB * 128 * 128];
__device__ float g_sums[NB * NS * 512];
__device__ int   g_cnt[NB * NS];

__device__ __forceinline__ int refl(int v, int n) {
    return v < 0 ? -v : (v >= n ? 2 * n - 2 - v : v);
}

__device__ __forceinline__ unsigned f2tf(float f) {
    unsigned u;
    asm("cvt.rna.tf32.f32 %0, %1;" : "=r"(u) : "f"(f));
    return u;
}

__device__ __forceinline__ void mma_tf32(float* c, const unsigned* a, const unsigned* b) {
    asm volatile(
        "mma.sync.aligned.m16n8k8.row.col.f32.tf32.tf32.f32 "
        "{%0,%1,%2,%3}, {%4,%5,%6,%7}, {%8,%9}, {%0,%1,%2,%3};"
        : "+f"(c[0]), "+f"(c[1]), "+f"(c[2]), "+f"(c[3])
        : "r"(a[0]), "r"(a[1]), "r"(a[2]), "r"(a[3]), "r"(b[0]), "r"(b[1]));
}

// ---------------------------------------------------------------------------
__global__ void k_zero_cnt() {
    int i = threadIdx.x;
    if (i < NB * NS) g_cnt[i] = 0;
}

// ---------------------------------------------------------------------------
// conv1: reflect pad, 3->32, 256x256 (scalar; tiny)
// ---------------------------------------------------------------------------
__global__ void k_conv1(const float* __restrict__ in, const float* __restrict__ w,
                        const float* __restrict__ bias) {
    int p = blockIdx.y;
    int b = p >> 5, co = p & 31;
    __shared__ float ws[27];
    __shared__ float bs;
    if (threadIdx.x < 27) ws[threadIdx.x] = w[co * 27 + threadIdx.x];
    if (threadIdx.x == 0) bs = bias[co];
    __syncthreads();
    int idx = blockIdx.x * 256 + threadIdx.x;
    int y = idx >> 8, x = idx & 255;
    int ry[3], rx[3];
#pragma unroll
    for (int k = 0; k < 3; k++) { ry[k] = refl(y - 1 + k, 256); rx[k] = refl(x - 1 + k, 256); }
    float acc = bs;
#pragma unroll
    for (int ci = 0; ci < 3; ci++) {
        const float* ip = in + ((size_t)(b * 3 + ci)) * 65536;
#pragma unroll
        for (int ky = 0; ky < 3; ky++) {
            const float* row = ip + ry[ky] * 256;
#pragma unroll
            for (int kx = 0; kx < 3; kx++)
                acc = fmaf(row[rx[kx]], ws[ci * 9 + ky * 3 + kx], acc);
        }
    }
    g_act1[(size_t)p * 65536 + idx] = acc;
}

// ---------------------------------------------------------------------------
// fused instance-norm + leaky relu (in place)
// ---------------------------------------------------------------------------
__global__ void k_in_lrelu(float* __restrict__ buf, int HW) {
    float* p = buf + (size_t)blockIdx.x * HW;
    float s = 0.f, s2 = 0.f;
    for (int i = threadIdx.x; i < HW; i += 256) {
        float v = p[i];
        s += v;
        s2 = fmaf(v, v, s2);
    }
#pragma unroll
    for (int o = 16; o; o >>= 1) {
        s  += __shfl_down_sync(0xffffffffu, s, o);
        s2 += __shfl_down_sync(0xffffffffu, s2, o);
    }
    __shared__ float sh[16];
    __shared__ float mr[2];
    int wid = threadIdx.x >> 5, lid = threadIdx.x & 31;
    if (lid == 0) { sh[wid] = s; sh[8 + wid] = s2; }
    __syncthreads();
    if (threadIdx.x == 0) {
        float ts = 0.f, t2 = 0.f;
        for (int j = 0; j < 8; j++) { ts += sh[j]; t2 += sh[8 + j]; }
        float inv = 1.0f / (float)HW;
        float m = ts * inv;
        float var = t2 * inv - m * m;
        mr[0] = m;
        mr[1] = rsqrtf(var + 1e-5f);
    }
    __syncthreads();
    float m = mr[0], r = mr[1];
    for (int i = threadIdx.x; i < HW; i += 256) {
        float v = (p[i] - m) * r;
        p[i] = v > 0.f ? v : 0.2f * v;
    }
}

// ---------------------------------------------------------------------------
// stride-2 conv via tf32 mma (k=3, p=1). 64 cout x 128 out-pixels per block.
// Halo per ci: 17 rows x 33 cols (zero-pad), ci stride 569.
// Weight chunk [64co][8ci*9tap] identical layout to conv5.
// grid: (HOUT/8 * HOUT/16, NB, COUT/64), 128 threads.
// ---------------------------------------------------------------------------
template <int CIN, int HIN>
__global__ __launch_bounds__(128) void k_conv_s2_mma(const float* __restrict__ in,
                                                     const float* __restrict__ w,
                                                     const float* __restrict__ bias,
                                                     float* __restrict__ out,
                                                     int cout_total) {
    constexpr int HOUT = HIN / 2;
    constexpr int XTILES = HOUT / 16;
    const int b = blockIdx.y;
    const int cog = blockIdx.z;
    const int y0 = (blockIdx.x / XTILES) * 8;   // output rows
    const int x0 = (blockIdx.x % XTILES) * 16;  // output cols

    const int tid = threadIdx.x;
    const int lane = tid & 31;
    const int ww = tid >> 5;
    const int mwarp = ww & 1;
    const int nwarp = ww >> 1;
    const int gid = lane >> 2;
    const int tig = lane & 3;

    __shared__ unsigned s_in[8 * 569];
    __shared__ unsigned s_w[64 * 72];

    float acc[2][8][4];
#pragma unroll
    for (int mt = 0; mt < 2; mt++)
#pragma unroll
        for (int j = 0; j < 8; j++)
#pragma unroll
            for (int q = 0; q < 4; q++) acc[mt][j][q] = 0.f;

    const float* inb = in + (size_t)b * CIN * HIN * HIN;
    const float* wb = w + (size_t)cog * 64 * CIN * 9;
    const int iy0 = 2 * y0 - 1, ix0 = 2 * x0 - 1;

    for (int cc = 0; cc < CIN / 8; cc++) {
        __syncthreads();
        // halo: 8 ci x 17 x 33, zero-padded
        for (int idx = tid; idx < 8 * 561; idx += 128) {
            int c = idx / 561, r = idx - c * 561;
            int rr = r / 33, cx = r - rr * 33;
            int gy = iy0 + rr, gx = ix0 + cx;
            float v = ((unsigned)gy < (unsigned)HIN && (unsigned)gx < (unsigned)HIN)
                          ? inb[((size_t)(cc * 8 + c) * HIN + gy) * HIN + gx]
                          : 0.f;
            s_in[c * 569 + rr * 33 + cx] = f2tf(v);
        }
        // weights: 64 co x 72 (8ci x 9tap contiguous in OIHW)
        for (int idx = tid; idx < 64 * 72; idx += 128) {
            int co = idx / 72, kk = idx - co * 72;
            s_w[co * 72 + kk] = f2tf(wb[(size_t)co * CIN * 9 + cc * 72 + kk]);
        }
        __syncthreads();

#pragma unroll
        for (int t = 0; t < 9; t++) {
            const int ky = t / 3, kx = t - ky * 3;
            unsigned a[2][4];
#pragma unroll
            for (int mt = 0; mt < 2; mt++) {
                int mrow = mwarp * 32 + mt * 16 + gid;
                a[mt][0] = s_w[mrow * 72 + tig * 9 + t];
                a[mt][1] = s_w[(mrow + 8) * 72 + tig * 9 + t];
                a[mt][2] = s_w[mrow * 72 + (tig + 4) * 9 + t];
                a[mt][3] = s_w[(mrow + 8) * 72 + (tig + 4) * 9 + t];
            }
#pragma unroll
            for (int j = 0; j < 8; j++) {
                int jj = nwarp * 8 + j;
                int row = jj >> 1;
                int xcol = (jj & 1) * 8;
                int hy = 2 * row + ky;
                int hx = 2 * (xcol + gid) + kx;
                unsigned bf[2];
                bf[0] = s_in[tig * 569 + hy * 33 + hx];
                bf[1] = s_in[(tig + 4) * 569 + hy * 33 + hx];
                mma_tf32(acc[0][j], a[0], bf);
                mma_tf32(acc[1][j], a[1], bf);
            }
        }
    }

#pragma unroll
    for (int mt = 0; mt < 2; mt++) {
        int co0 = cog * 64 + mwarp * 32 + mt * 16 + gid;
        float bs0 = bias[co0];
        float bs1 = bias[co0 + 8];
#pragma unroll
        for (int j = 0; j < 8; j++) {
            int jj = nwarp * 8 + j;
            int y = y0 + (jj >> 1);
            int x = x0 + (jj & 1) * 8 + 2 * tig;
            float2 v0 = make_float2(acc[mt][j][0] + bs0, acc[mt][j][1] + bs0);
            float2 v1 = make_float2(acc[mt][j][2] + bs1, acc[mt][j][3] + bs1);
            *(float2*)&out[(((size_t)(b * cout_total + co0)) * HOUT + y) * HOUT + x] = v0;
            *(float2*)&out[(((size_t)(b * cout_total + co0 + 8)) * HOUT + y) * HOUT + x] = v1;
        }
    }
}

// ---------------------------------------------------------------------------
// convT via tf32 mma: [B,128,64,64] -> [B,256,128,128], per parity class.
// ---------------------------------------------------------------------------
__global__ __launch_bounds__(128) void k_convT_mma(const float* __restrict__ in,
                                                   const float* __restrict__ w,
                                                   const float* __restrict__ bias,
                                                   float* __restrict__ out) {
    const int b = blockIdx.y;
    const int z = blockIdx.z;
    const int cog = z >> 2, cls = z & 3;
    const int py = cls >> 1, px = cls & 1;
    const int y0 = (blockIdx.x >> 2) * 8;
    const int x0 = (blockIdx.x & 3) * 16;

    const int tid = threadIdx.x;
    const int lane = tid & 31;
    const int ww = tid >> 5;
    const int mwarp = ww & 1;
    const int nwarp = ww >> 1;
    const int gid = lane >> 2;
    const int tig = lane & 3;

    int nky = py ? 2 : 1, nkx = px ? 2 : 1;
    int kyA[2] = {1, 0}, dyA[2] = {0, 0};
    if (py) { kyA[0] = 0; dyA[0] = 1; kyA[1] = 2; dyA[1] = 0; }
    int kxA[2] = {1, 0}, dxA[2] = {0, 0};
    if (px) { kxA[0] = 0; dxA[0] = 1; kxA[1] = 2; dxA[1] = 0; }
    const int ntaps = nky * nkx;
    int tval[4], tdy[4], tdx[4];
    for (int a = 0; a < nky; a++)
        for (int e = 0; e < nkx; e++) {
            int ta = a * nkx + e;
            tval[ta] = kyA[a] * 3 + kxA[e];
            tdy[ta] = dyA[a];
            tdx[ta] = dxA[e];
        }

    __shared__ unsigned s_in[8 * 168];
    __shared__ unsigned s_w[4 * 64 * 12];

    float acc[2][8][4];
#pragma unroll
    for (int mt = 0; mt < 2; mt++)
#pragma unroll
        for (int j = 0; j < 8; j++)
#pragma unroll
            for (int q = 0; q < 4; q++) acc[mt][j][q] = 0.f;

    const float* inb = in + (size_t)b * 128 * 4096;

    for (int cc = 0; cc < 16; cc++) {
        __syncthreads();
        for (int idx = tid; idx < 8 * 153; idx += 128) {
            int c = idx / 153, r = idx - c * 153;
            int rr = r / 17, cx = r - rr * 17;
            int gy = y0 + rr, gx = x0 + cx;
            float v = (gy < 64 && gx < 64)
                          ? inb[((size_t)(cc * 8 + c) * 64 + gy) * 64 + gx]
                          : 0.f;
            s_in[c * 168 + rr * 17 + cx] = f2tf(v);
        }
        for (int idx = tid; idx < ntaps * 512; idx += 128) {
            int ta = idx >> 9;
            int rem = idx & 511;
            int co = rem >> 3, q = rem & 7;
            float v = w[(((size_t)(cc * 8 + q)) * 256 + cog * 64 + co) * 9 + tval[ta]];
            s_w[(ta * 64 + co) * 12 + q] = f2tf(v);
        }
        __syncthreads();

        for (int ta = 0; ta < ntaps; ta++) {
            unsigned a[2][4];
#pragma unroll
            for (int mt = 0; mt < 2; mt++) {
                int mrow = mwarp * 32 + mt * 16 + gid;
                a[mt][0] = s_w[(ta * 64 + mrow) * 12 + tig];
                a[mt][1] = s_w[(ta * 64 + mrow + 8) * 12 + tig];
                a[mt][2] = s_w[(ta * 64 + mrow) * 12 + tig + 4];
                a[mt][3] = s_w[(ta * 64 + mrow + 8) * 12 + tig + 4];
            }
            int dy = tdy[ta], dx = tdx[ta];
#pragma unroll
            for (int j = 0; j < 8; j++) {
                int jj = nwarp * 8 + j;
                int hy = (jj >> 1) + dy;
                int hx = (jj & 1) * 8 + gid + dx;
                unsigned bf[2];
                bf[0] = s_in[tig * 168 + hy * 17 + hx];
                bf[1] = s_in[(tig + 4) * 168 + hy * 17 + hx];
                mma_tf32(acc[0][j], a[0], bf);
                mma_tf32(acc[1][j], a[1], bf);
            }
        }
    }

#pragma unroll
    for (int mt = 0; mt < 2; mt++) {
        int co0 = cog * 64 + mwarp * 32 + mt * 16 + gid;
        float bs0 = bias[co0];
        float bs1 = bias[co0 + 8];
#pragma unroll
        for (int j = 0; j < 8; j++) {
            int jj = nwarp * 8 + j;
            int yc = y0 + (jj >> 1);
            int xc = x0 + (jj & 1) * 8 + 2 * tig;
            int y = 2 * yc + py;
            int x = 2 * xc + px;
            size_t o0 = (((size_t)(b * 256 + co0)) * 128 + y) * 128 + x;
            size_t o1 = (((size_t)(b * 256 + co0 + 8)) * 128 + y) * 128 + x;
            out[o0] = acc[mt][j][0] + bs0;
            out[o0 + 2] = acc[mt][j][1] + bs0;
            out[o1] = acc[mt][j][2] + bs1;
            out[o1 + 2] = acc[mt][j][3] + bs1;
        }
    }
}

// ---------------------------------------------------------------------------
// conv5 via tf32 mma, 2-wide pixel tile (8x32 region = 256 px per block).
// 64 cout x 256 px; 4 warps (2m x 2n), each warp 32co x 128px = 2mt x 16nt.
// Halo: 8 ci x 10 x 34, ci stride 344 (conflict-free B-frag LDS).
// grid (64, NB, 8), 128 threads.
// ---------------------------------------------------------------------------
__global__ __launch_bounds__(128) void k_conv5_mma(const float* __restrict__ in,
                                                   const float* __restrict__ w,
                                                   const float* __restrict__ bias,
                                                   float* __restrict__ out) {
    const int b = blockIdx.y;
    const int cog = blockIdx.z;
    const int y0 = (blockIdx.x >> 2) * 8;
    const int x0 = (blockIdx.x & 3) * 32;

    const int tid = threadIdx.x;
    const int lane = tid & 31;
    const int ww = tid >> 5;
    const int mwarp = ww & 1;
    const int nwarp = ww >> 1;
    const int gid = lane >> 2;
    const int tig = lane & 3;

    __shared__ unsigned s_in[8 * 344];
    __shared__ unsigned s_w[64 * 72];

    float acc[2][16][4];
#pragma unroll
    for (int mt = 0; mt < 2; mt++)
#pragma unroll
        for (int j = 0; j < 16; j++)
#pragma unroll
            for (int q = 0; q < 4; q++) acc[mt][j][q] = 0.f;

    const float* inb = in + (size_t)b * 256 * 16384;
    const float* wb = w + (size_t)cog * 64 * 2304;

    for (int cc = 0; cc < 32; cc++) {
        __syncthreads();
        // halo: 8 ci x 10 rows x 34 cols, reflect
        for (int idx = tid; idx < 8 * 340; idx += 128) {
            int c = idx / 340, r = idx - c * 340;
            int yy = r / 34, xx = r - yy * 34;
            int gy = refl(y0 - 1 + yy, 128);
            int gx = refl(x0 - 1 + xx, 128);
            s_in[c * 344 + yy * 34 + xx] =
                f2tf(inb[((size_t)(cc * 8 + c) * 128 + gy) * 128 + gx]);
        }
        for (int idx = tid; idx < 64 * 72; idx += 128) {
            int co = idx / 72, kk = idx - co * 72;
            s_w[co * 72 + kk] = f2tf(wb[(size_t)co * 2304 + cc * 72 + kk]);
        }
        __syncthreads();

#pragma unroll
        for (int t = 0; t < 9; t++) {
            const int ky = t / 3, kx = t - ky * 3;
            unsigned a[2][4];
#pragma unroll
            for (int mt = 0; mt < 2; mt++) {
                int mrow = mwarp * 32 + mt * 16 + gid;
                a[mt][0] = s_w[mrow * 72 + tig * 9 + t];
                a[mt][1] = s_w[(mrow + 8) * 72 + tig * 9 + t];
                a[mt][2] = s_w[mrow * 72 + (tig + 4) * 9 + t];
                a[mt][3] = s_w[(mrow + 8) * 72 + (tig + 4) * 9 + t];
            }
#pragma unroll
            for (int j = 0; j < 16; j++) {
                int jj = nwarp * 16 + j;
                int row = jj >> 2;
                int xcol = (jj & 3) * 8;
                int hy = row + ky;
                int hx = xcol + gid + kx;
                unsigned bf[2];
                bf[0] = s_in[tig * 344 + hy * 34 + hx];
                bf[1] = s_in[(tig + 4) * 344 + hy * 34 + hx];
                mma_tf32(acc[0][j], a[0], bf);
                mma_tf32(acc[1][j], a[1], bf);
            }
        }
    }

    const int coutA = cog * 64 + mwarp * 32;
#pragma unroll
    for (int mt = 0; mt < 2; mt++) {
        int co0 = coutA + mt * 16 + gid;
        float bs0 = bias[co0];
        float bs1 = bias[co0 + 8];
#pragma unroll
        for (int j = 0; j < 16; j++) {
            int jj = nwarp * 16 + j;
            int y = y0 + (jj >> 2);
            int x = x0 + (jj & 3) * 8 + 2 * tig;
            float2 v0 = make_float2(tanhf(acc[mt][j][0] + bs0), tanhf(acc[mt][j][1] + bs0));
            float2 v1 = make_float2(tanhf(acc[mt][j][2] + bs1), tanhf(acc[mt][j][3] + bs1));
            *(float2*)&out[(((size_t)(b * 512 + co0)) * 128 + y) * 128 + x] = v0;
            *(float2*)&out[(((size_t)(b * 512 + co0 + 8)) * 128 + y) * 128 + x] = v1;
        }
    }
}

// ---------------------------------------------------------------------------
// labels + counts (nearest 256->128 = (2h,2w)); non-divergent class loop
// ---------------------------------------------------------------------------
__global__ void k_label(const float* __restrict__ seg) {
    int b = blockIdx.y;
    int i = blockIdx.x * 256 + threadIdx.x;
    int h = i >> 7, wv = i & 127;
    const float* sp = seg + (size_t)b * NS * 65536 + (2 * h) * 256 + 2 * wv;
    int lab = 0;
#pragma unroll 1
    for (int s = 0; s < NS; s++) {
        float v = sp[(size_t)s * 65536];
        if (v > 0.f) lab = s;   // one-hot: exactly one hit
    }
    g_label[b * 16384 + i] = lab;
    atomicAdd(&g_cnt[b * NS + lab], 1);
}

// ---------------------------------------------------------------------------
// segment-sum pooling, vectorized
// ---------------------------------------------------------------------------
__global__ void k_pool(const float* __restrict__ codes) {
    int c = blockIdx.x & 511;
    int b = blockIdx.x >> 9;
    __shared__ float bins[NS * 8];
    if (threadIdx.x < NS * 8) bins[threadIdx.x] = 0.f;
    __syncthreads();
    const float4* cp = (const float4*)(codes + ((size_t)(b * 512 + c)) * 16384);
    const int4* lp = (const int4*)(g_label + b * 16384);
    int sub = threadIdx.x & 7;
    for (int i = threadIdx.x; i < 4096; i += 256) {
        float4 v = cp[i];
        int4 l = lp[i];
        atomicAdd(&bins[l.x * 8 + sub], v.x);
        atomicAdd(&bins[l.y * 8 + sub], v.y);
        atomicAdd(&bins[l.z * 8 + sub], v.z);
        atomicAdd(&bins[l.w * 8 + sub], v.w);
    }
    __syncthreads();
    if (threadIdx.x < NS) {
        float s = 0.f;
#pragma unroll
        for (int j = 0; j < 8; j++) s += bins[threadIdx.x * 8 + j];
        g_sums[((size_t)b * NS + threadIdx.x) * 512 + c] = s;
    }
}

// ---------------------------------------------------------------------------
__global__ void k_final(float* __restrict__ out) {
    int idx = blockIdx.x * 256 + threadIdx.x;
    if (idx >= NB * NS * 512) return;
    int bs = idx >> 9;
    int cnt = g_cnt[bs];
    out[idx] = cnt > 0 ? g_sums[idx] / (float)cnt : 0.f;
}

// ---------------------------------------------------------------------------
extern "C" void kernel_launch(void* const* d_in, const int* in_sizes, int n_in,
                              void* d_out, int out_size) {
    const float* input  = (const float*)d_in[0];
    const float* segmap = (const float*)d_in[1];
    const float* w1 = (const float*)d_in[2];
    const float* b1 = (const float*)d_in[3];
    const float* w2 = (const float*)d_in[4];
    const float* b2 = (const float*)d_in[5];
    const float* w3 = (const float*)d_in[6];
    const float* b3 = (const float*)d_in[7];
    const float* w4 = (const float*)d_in[8];
    const float* b4 = (const float*)d_in[9];
    const float* w5 = (const float*)d_in[10];
    const float* b5 = (const float*)d_in[11];
    float* out = (float*)d_out;

    float* act1;  cudaGetSymbolAddress((void**)&act1, g_act1);
    float* act2;  cudaGetSymbolAddress((void**)&act2, g_act2);
    float* act3;  cudaGetSymbolAddress((void**)&act3, g_act3);
    float* act4;  cudaGetSymbolAddress((void**)&act4, g_act4);
    float* codes; cudaGetSymbolAddress((void**)&codes, g_codes);

    k_zero_cnt<<<1, 256>>>();

    // L1
    k_conv1<<<dim3(256, NB * 32), 256>>>(input, w1, b1);
    k_in_lrelu<<<NB * 32, 256>>>(act1, 65536);
    // L2: 32->64 @128x128 out; tiles 16x8=128
    k_conv_s2_mma<32, 256><<<dim3(128, NB, 1), 128>>>(act1, w2, b2, act2, 64);
    k_in_lrelu<<<NB * 64, 256>>>(act2, 16384);
    // L3: 64->128 @64x64 out; tiles 8x4=32
    k_conv_s2_mma<64, 128><<<dim3(32, NB, 2), 128>>>(act2, w3, b3, act3, 128);
    k_in_lrelu<<<NB * 128, 256>>>(act3, 4096);
    // L4 (transposed conv, tf32 mma)
    k_convT_mma<<<dim3(32, NB, 16), 128>>>(act3, w4, b4, act4);
    k_in_lrelu<<<NB * 256, 256>>>(act4, 16384);
    // L5 (+tanh, tf32 mma, 2-wide tiles)
    k_conv5_mma<<<dim3(64, NB, 8), 128>>>(act4, w5, b5, codes);
    // pooling
    k_label<<<dim3(64, NB), 256>>>(segmap);
    k_pool<<<NB * 512, 256>>>(codes);
    k_final<<<(NB * NS * 512 + 255) / 256, 256>>>(out);
}

// round 5
// speedup vs baseline: 1.1379x; 1.1379x over previous
#include <cuda_runtime.h>
#include <cuda_bf16.h>
#include <math.h>

// ---------------------------------------------------------------------------
// B=8; input [8,3,256,256]; segmap [8,19,256,256]
// L1: reflect-pad conv 3->32, 256x256, IN, lrelu       (scalar)
// L2: conv s2 p1 32->64, 128x128, IN, lrelu            (tf32 mma)
// L3: conv s2 p1 64->128, 64x64, IN, lrelu             (tf32 mma)
// L4: convT s2 p1 op1 128->256, 128x128, IN, lrelu     (tf32 mma per parity class)
// L5: reflect-pad conv 256->512, 128x128, tanh         (tf32 mma, 8x16 tile)
// pool: nearest one-hot segmap -> region means -> out [8,19,512]
// ---------------------------------------------------------------------------

#define NB 8
#define NS 19

__device__ float g_act1[NB * 32 * 256 * 256];
__device__ float g_act2[NB * 64 * 128 * 128];
__device__ float g_act3[NB * 128 * 64 * 64];
__device__ float g_act4[NB * 256 * 128 * 128];
__device__ float g_codes[(size_t)NB * 512 * 128 * 128];
__device__ int   g_label[NB * 128 * 128];
__device__ float g_sums[NB * NS * 512];
__device__ int   g_cnt[NB * NS];

__device__ __forceinline__ int refl(int v, int n) {
    return v < 0 ? -v : (v >= n ? 2 * n - 2 - v : v);
}

__device__ __forceinline__ unsigned f2tf(float f) {
    unsigned u;
    asm("cvt.rna.tf32.f32 %0, %1;" : "=r"(u) : "f"(f));
    return u;
}

__device__ __forceinline__ void mma_tf32(float* c, const unsigned* a, const unsigned* b) {
    asm volatile(
        "mma.sync.aligned.m16n8k8.row.col.f32.tf32.tf32.f32 "
        "{%0,%1,%2,%3}, {%4,%5,%6,%7}, {%8,%9}, {%0,%1,%2,%3};"
        : "+f"(c[0]), "+f"(c[1]), "+f"(c[2]), "+f"(c[3])
        : "r"(a[0]), "r"(a[1]), "r"(a[2]), "r"(a[3]), "r"(b[0]), "r"(b[1]));
}

// ---------------------------------------------------------------------------
__global__ void k_zero_cnt() {
    int i = threadIdx.x;
    if (i < NB * NS) g_cnt[i] = 0;
}

// ---------------------------------------------------------------------------
// conv1: reflect pad, 3->32, 256x256 (scalar; tiny)
// ---------------------------------------------------------------------------
__global__ void k_conv1(const float* __restrict__ in, const float* __restrict__ w,
                        const float* __restrict__ bias) {
    int p = blockIdx.y;
    int b = p >> 5, co = p & 31;
    __shared__ float ws[27];
    __shared__ float bs;
    if (threadIdx.x < 27) ws[threadIdx.x] = w[co * 27 + threadIdx.x];
    if (threadIdx.x == 0) bs = bias[co];
    __syncthreads();
    int idx = blockIdx.x * 256 + threadIdx.x;
    int y = idx >> 8, x = idx & 255;
    int ry[3], rx[3];
#pragma unroll
    for (int k = 0; k < 3; k++) { ry[k] = refl(y - 1 + k, 256); rx[k] = refl(x - 1 + k, 256); }
    float acc = bs;
#pragma unroll
    for (int ci = 0; ci < 3; ci++) {
        const float* ip = in + ((size_t)(b * 3 + ci)) * 65536;
#pragma unroll
        for (int ky = 0; ky < 3; ky++) {
            const float* row = ip + ry[ky] * 256;
#pragma unroll
            for (int kx = 0; kx < 3; kx++)
                acc = fmaf(row[rx[kx]], ws[ci * 9 + ky * 3 + kx], acc);
        }
    }
    g_act1[(size_t)p * 65536 + idx] = acc;
}

// ---------------------------------------------------------------------------
// fused instance-norm + leaky relu (in place)
// ---------------------------------------------------------------------------
__global__ void k_in_lrelu(float* __restrict__ buf, int HW) {
    float* p = buf + (size_t)blockIdx.x * HW;
    float s = 0.f, s2 = 0.f;
    for (int i = threadIdx.x; i < HW; i += 256) {
        float v = p[i];
        s += v;
        s2 = fmaf(v, v, s2);
    }
#pragma unroll
    for (int o = 16; o; o >>= 1) {
        s  += __shfl_down_sync(0xffffffffu, s, o);
        s2 += __shfl_down_sync(0xffffffffu, s2, o);
    }
    __shared__ float sh[16];
    __shared__ float mr[2];
    int wid = threadIdx.x >> 5, lid = threadIdx.x & 31;
    if (lid == 0) { sh[wid] = s; sh[8 + wid] = s2; }
    __syncthreads();
    if (threadIdx.x == 0) {
        float ts = 0.f, t2 = 0.f;
        for (int j = 0; j < 8; j++) { ts += sh[j]; t2 += sh[8 + j]; }
        float inv = 1.0f / (float)HW;
        float m = ts * inv;
        float var = t2 * inv - m * m;
        mr[0] = m;
        mr[1] = rsqrtf(var + 1e-5f);
    }
    __syncthreads();
    float m = mr[0], r = mr[1];
    for (int i = threadIdx.x; i < HW; i += 256) {
        float v = (p[i] - m) * r;
        p[i] = v > 0.f ? v : 0.2f * v;
    }
}

// ---------------------------------------------------------------------------
// stride-2 conv via tf32 mma (k=3, p=1). 64 cout x 128 out-pixels per block.
// ---------------------------------------------------------------------------
template <int CIN, int HIN>
__global__ __launch_bounds__(128) void k_conv_s2_mma(const float* __restrict__ in,
                                                     const float* __restrict__ w,
                                                     const float* __restrict__ bias,
                                                     float* __restrict__ out,
                                                     int cout_total) {
    constexpr int HOUT = HIN / 2;
    constexpr int XTILES = HOUT / 16;
    const int b = blockIdx.y;
    const int cog = blockIdx.z;
    const int y0 = (blockIdx.x / XTILES) * 8;
    const int x0 = (blockIdx.x % XTILES) * 16;

    const int tid = threadIdx.x;
    const int lane = tid & 31;
    const int ww = tid >> 5;
    const int mwarp = ww & 1;
    const int nwarp = ww >> 1;
    const int gid = lane >> 2;
    const int tig = lane & 3;

    __shared__ unsigned s_in[8 * 569];
    __shared__ unsigned s_w[64 * 72];

    float acc[2][8][4];
#pragma unroll
    for (int mt = 0; mt < 2; mt++)
#pragma unroll
        for (int j = 0; j < 8; j++)
#pragma unroll
            for (int q = 0; q < 4; q++) acc[mt][j][q] = 0.f;

    const float* inb = in + (size_t)b * CIN * HIN * HIN;
    const float* wb = w + (size_t)cog * 64 * CIN * 9;
    const int iy0 = 2 * y0 - 1, ix0 = 2 * x0 - 1;

    for (int cc = 0; cc < CIN / 8; cc++) {
        __syncthreads();
        for (int idx = tid; idx < 8 * 561; idx += 128) {
            int c = idx / 561, r = idx - c * 561;
            int rr = r / 33, cx = r - rr * 33;
            int gy = iy0 + rr, gx = ix0 + cx;
            float v = ((unsigned)gy < (unsigned)HIN && (unsigned)gx < (unsigned)HIN)
                          ? inb[((size_t)(cc * 8 + c) * HIN + gy) * HIN + gx]
                          : 0.f;
            s_in[c * 569 + rr * 33 + cx] = f2tf(v);
        }
        for (int idx = tid; idx < 64 * 72; idx += 128) {
            int co = idx / 72, kk = idx - co * 72;
            s_w[co * 72 + kk] = f2tf(wb[(size_t)co * CIN * 9 + cc * 72 + kk]);
        }
        __syncthreads();

#pragma unroll
        for (int t = 0; t < 9; t++) {
            const int ky = t / 3, kx = t - ky * 3;
            unsigned a[2][4];
#pragma unroll
            for (int mt = 0; mt < 2; mt++) {
                int mrow = mwarp * 32 + mt * 16 + gid;
                a[mt][0] = s_w[mrow * 72 + tig * 9 + t];
                a[mt][1] = s_w[(mrow + 8) * 72 + tig * 9 + t];
                a[mt][2] = s_w[mrow * 72 + (tig + 4) * 9 + t];
                a[mt][3] = s_w[(mrow + 8) * 72 + (tig + 4) * 9 + t];
            }
#pragma unroll
            for (int j = 0; j < 8; j++) {
                int jj = nwarp * 8 + j;
                int row = jj >> 1;
                int xcol = (jj & 1) * 8;
                int hy = 2 * row + ky;
                int hx = 2 * (xcol + gid) + kx;
                unsigned bf[2];
                bf[0] = s_in[tig * 569 + hy * 33 + hx];
                bf[1] = s_in[(tig + 4) * 569 + hy * 33 + hx];
                mma_tf32(acc[0][j], a[0], bf);
                mma_tf32(acc[1][j], a[1], bf);
            }
        }
    }

#pragma unroll
    for (int mt = 0; mt < 2; mt++) {
        int co0 = cog * 64 + mwarp * 32 + mt * 16 + gid;
        float bs0 = bias[co0];
        float bs1 = bias[co0 + 8];
#pragma unroll
        for (int j = 0; j < 8; j++) {
            int jj = nwarp * 8 + j;
            int y = y0 + (jj >> 1);
            int x = x0 + (jj & 1) * 8 + 2 * tig;
            float2 v0 = make_float2(acc[mt][j][0] + bs0, acc[mt][j][1] + bs0);
            float2 v1 = make_float2(acc[mt][j][2] + bs1, acc[mt][j][3] + bs1);
            *(float2*)&out[(((size_t)(b * cout_total + co0)) * HOUT + y) * HOUT + x] = v0;
            *(float2*)&out[(((size_t)(b * cout_total + co0 + 8)) * HOUT + y) * HOUT + x] = v1;
        }
    }
}

// ---------------------------------------------------------------------------
// convT via tf32 mma: [B,128,64,64] -> [B,256,128,128], per parity class.
// ---------------------------------------------------------------------------
__global__ __launch_bounds__(128) void k_convT_mma(const float* __restrict__ in,
                                                   const float* __restrict__ w,
                                                   const float* __restrict__ bias,
                                                   float* __restrict__ out) {
    const int b = blockIdx.y;
    const int z = blockIdx.z;
    const int cog = z >> 2, cls = z & 3;
    const int py = cls >> 1, px = cls & 1;
    const int y0 = (blockIdx.x >> 2) * 8;
    const int x0 = (blockIdx.x & 3) * 16;

    const int tid = threadIdx.x;
    const int lane = tid & 31;
    const int ww = tid >> 5;
    const int mwarp = ww & 1;
    const int nwarp = ww >> 1;
    const int gid = lane >> 2;
    const int tig = lane & 3;

    int nky = py ? 2 : 1, nkx = px ? 2 : 1;
    int kyA[2] = {1, 0}, dyA[2] = {0, 0};
    if (py) { kyA[0] = 0; dyA[0] = 1; kyA[1] = 2; dyA[1] = 0; }
    int kxA[2] = {1, 0}, dxA[2] = {0, 0};
    if (px) { kxA[0] = 0; dxA[0] = 1; kxA[1] = 2; dxA[1] = 0; }
    const int ntaps = nky * nkx;
    int tval[4], tdy[4], tdx[4];
    for (int a = 0; a < nky; a++)
        for (int e = 0; e < nkx; e++) {
            int ta = a * nkx + e;
            tval[ta] = kyA[a] * 3 + kxA[e];
            tdy[ta] = dyA[a];
            tdx[ta] = dxA[e];
        }

    __shared__ unsigned s_in[8 * 168];
    __shared__ unsigned s_w[4 * 64 * 12];

    float acc[2][8][4];
#pragma unroll
    for (int mt = 0; mt < 2; mt++)
#pragma unroll
        for (int j = 0; j < 8; j++)
#pragma unroll
            for (int q = 0; q < 4; q++) acc[mt][j][q] = 0.f;

    const float* inb = in + (size_t)b * 128 * 4096;

    for (int cc = 0; cc < 16; cc++) {
        __syncthreads();
        for (int idx = tid; idx < 8 * 153; idx += 128) {
            int c = idx / 153, r = idx - c * 153;
            int rr = r / 17, cx = r - rr * 17;
            int gy = y0 + rr, gx = x0 + cx;
            float v = (gy < 64 && gx < 64)
                          ? inb[((size_t)(cc * 8 + c) * 64 + gy) * 64 + gx]
                          : 0.f;
            s_in[c * 168 + rr * 17 + cx] = f2tf(v);
        }
        for (int idx = tid; idx < ntaps * 512; idx += 128) {
            int ta = idx >> 9;
            int rem = idx & 511;
            int co = rem >> 3, q = rem & 7;
            float v = w[(((size_t)(cc * 8 + q)) * 256 + cog * 64 + co) * 9 + tval[ta]];
            s_w[(ta * 64 + co) * 12 + q] = f2tf(v);
        }
        __syncthreads();

        for (int ta = 0; ta < ntaps; ta++) {
            unsigned a[2][4];
#pragma unroll
            for (int mt = 0; mt < 2; mt++) {
                int mrow = mwarp * 32 + mt * 16 + gid;
                a[mt][0] = s_w[(ta * 64 + mrow) * 12 + tig];
                a[mt][1] = s_w[(ta * 64 + mrow + 8) * 12 + tig];
                a[mt][2] = s_w[(ta * 64 + mrow) * 12 + tig + 4];
                a[mt][3] = s_w[(ta * 64 + mrow + 8) * 12 + tig + 4];
            }
            int dy = tdy[ta], dx = tdx[ta];
#pragma unroll
            for (int j = 0; j < 8; j++) {
                int jj = nwarp * 8 + j;
                int hy = (jj >> 1) + dy;
                int hx = (jj & 1) * 8 + gid + dx;
                unsigned bf[2];
                bf[0] = s_in[tig * 168 + hy * 17 + hx];
                bf[1] = s_in[(tig + 4) * 168 + hy * 17 + hx];
                mma_tf32(acc[0][j], a[0], bf);
                mma_tf32(acc[1][j], a[1], bf);
            }
        }
    }

#pragma unroll
    for (int mt = 0; mt < 2; mt++) {
        int co0 = cog * 64 + mwarp * 32 + mt * 16 + gid;
        float bs0 = bias[co0];
        float bs1 = bias[co0 + 8];
#pragma unroll
        for (int j = 0; j < 8; j++) {
            int jj = nwarp * 8 + j;
            int yc = y0 + (jj >> 1);
            int xc = x0 + (jj & 1) * 8 + 2 * tig;
            int y = 2 * yc + py;
            int x = 2 * xc + px;
            size_t o0 = (((size_t)(b * 256 + co0)) * 128 + y) * 128 + x;
            size_t o1 = (((size_t)(b * 256 + co0 + 8)) * 128 + y) * 128 + x;
            out[o0] = acc[mt][j][0] + bs0;
            out[o0 + 2] = acc[mt][j][1] + bs0;
            out[o1] = acc[mt][j][2] + bs1;
            out[o1 + 2] = acc[mt][j][3] + bs1;
        }
    }
}

// ---------------------------------------------------------------------------
// conv5 via tf32 mma (proven R3 tiling): 64 cout x 128 px (8x16), grid (128,B,8)
// ---------------------------------------------------------------------------
__global__ __launch_bounds__(128) void k_conv5_mma(const float* __restrict__ in,
                                                   const float* __restrict__ w,
                                                   const float* __restrict__ bias,
                                                   float* __restrict__ out) {
    const int b = blockIdx.y;
    const int cog = blockIdx.z;
    const int y0 = (blockIdx.x >> 3) * 8;
    const int x0 = (blockIdx.x & 7) * 16;

    const int tid = threadIdx.x;
    const int lane = tid & 31;
    const int ww = tid >> 5;
    const int mwarp = ww & 1;
    const int nwarp = ww >> 1;
    const int gid = lane >> 2;
    const int tig = lane & 3;

    __shared__ unsigned s_in[8 * 184];
    __shared__ unsigned s_w[64 * 72];

    float acc[2][8][4];
#pragma unroll
    for (int mt = 0; mt < 2; mt++)
#pragma unroll
        for (int j = 0; j < 8; j++)
#pragma unroll
            for (int q = 0; q < 4; q++) acc[mt][j][q] = 0.f;

    const float* inb = in + (size_t)b * 256 * 16384;
    const float* wb = w + (size_t)cog * 64 * 2304;

    for (int cc = 0; cc < 32; cc++) {
        __syncthreads();
        for (int idx = tid; idx < 8 * 180; idx += 128) {
            int c = idx / 180, r = idx - c * 180;
            int yy = r / 18, xx = r - yy * 18;
            int gy = refl(y0 - 1 + yy, 128);
            int gx = refl(x0 - 1 + xx, 128);
            s_in[c * 184 + yy * 18 + xx] =
                f2tf(inb[((size_t)(cc * 8 + c) * 128 + gy) * 128 + gx]);
        }
        for (int idx = tid; idx < 64 * 72; idx += 128) {
            int co = idx / 72, kk = idx - co * 72;
            s_w[co * 72 + kk] = f2tf(wb[(size_t)co * 2304 + cc * 72 + kk]);
        }
        __syncthreads();

#pragma unroll
        for (int t = 0; t < 9; t++) {
            const int ky = t / 3, kx = t - ky * 3;
            unsigned a[2][4];
#pragma unroll
            for (int mt = 0; mt < 2; mt++) {
                int mrow = mwarp * 32 + mt * 16 + gid;
                a[mt][0] = s_w[mrow * 72 + tig * 9 + t];
                a[mt][1] = s_w[(mrow + 8) * 72 + tig * 9 + t];
                a[mt][2] = s_w[mrow * 72 + (tig + 4) * 9 + t];
                a[mt][3] = s_w[(mrow + 8) * 72 + (tig + 4) * 9 + t];
            }
            unsigned bcur[2], bnxt[2];
            {
                int jj = nwarp * 8;
                int hy = (jj >> 1) + ky;
                int hx = (jj & 1) * 8 + gid + kx;
                bcur[0] = s_in[tig * 184 + hy * 18 + hx];
                bcur[1] = s_in[(tig + 4) * 184 + hy * 18 + hx];
            }
#pragma unroll
            for (int j = 0; j < 8; j++) {
                if (j < 7) {
                    int jj = nwarp * 8 + j + 1;
                    int hy = (jj >> 1) + ky;
                    int hx = (jj & 1) * 8 + gid + kx;
                    bnxt[0] = s_in[tig * 184 + hy * 18 + hx];
                    bnxt[1] = s_in[(tig + 4) * 184 + hy * 18 + hx];
                }
                mma_tf32(acc[0][j], a[0], bcur);
                mma_tf32(acc[1][j], a[1], bcur);
                bcur[0] = bnxt[0];
                bcur[1] = bnxt[1];
            }
        }
    }

    const int coutA = cog * 64 + mwarp * 32;
#pragma unroll
    for (int mt = 0; mt < 2; mt++) {
        int co0 = coutA + mt * 16 + gid;
        float bs0 = bias[co0];
        float bs1 = bias[co0 + 8];
#pragma unroll
        for (int j = 0; j < 8; j++) {
            int jj = nwarp * 8 + j;
            int y = y0 + (jj >> 1);
            int x = x0 + (jj & 1) * 8 + 2 * tig;
            float2 v0 = make_float2(tanhf(acc[mt][j][0] + bs0), tanhf(acc[mt][j][1] + bs0));
            float2 v1 = make_float2(tanhf(acc[mt][j][2] + bs1), tanhf(acc[mt][j][3] + bs1));
            *(float2*)&out[(((size_t)(b * 512 + co0)) * 128 + y) * 128 + x] = v0;
            *(float2*)&out[(((size_t)(b * 512 + co0 + 8)) * 128 + y) * 128 + x] = v1;
        }
    }
}

// ---------------------------------------------------------------------------
// labels + counts (nearest 256->128 = (2h,2w))
// ---------------------------------------------------------------------------
__global__ void k_label(const float* __restrict__ seg) {
    int b = blockIdx.y;
    int i = blockIdx.x * 256 + threadIdx.x;
    int h = i >> 7, wv = i & 127;
    const float* sp = seg + (size_t)b * NS * 65536 + (2 * h) * 256 + 2 * wv;
    int lab = 0;
#pragma unroll 1
    for (int s = 0; s < NS; s++) {
        float v = sp[(size_t)s * 65536];
        if (v > 0.f) lab = s;
    }
    g_label[b * 16384 + i] = lab;
    atomicAdd(&g_cnt[b * NS + lab], 1);
}

// ---------------------------------------------------------------------------
// segment-sum pooling, vectorized
// ---------------------------------------------------------------------------
__global__ void k_pool(const float* __restrict__ codes) {
    int c = blockIdx.x & 511;
    int b = blockIdx.x >> 9;
    __shared__ float bins[NS * 8];
    if (threadIdx.x < NS * 8) bins[threadIdx.x] = 0.f;
    __syncthreads();
    const float4* cp = (const float4*)(codes + ((size_t)(b * 512 + c)) * 16384);
    const int4* lp = (const int4*)(g_label + b * 16384);
    int sub = threadIdx.x & 7;
    for (int i = threadIdx.x; i < 4096; i += 256) {
        float4 v = cp[i];
        int4 l = lp[i];
        atomicAdd(&bins[l.x * 8 + sub], v.x);
        atomicAdd(&bins[l.y * 8 + sub], v.y);
        atomicAdd(&bins[l.z * 8 + sub], v.z);
        atomicAdd(&bins[l.w * 8 + sub], v.w);
    }
    __syncthreads();
    if (threadIdx.x < NS) {
        float s = 0.f;
#pragma unroll
        for (int j = 0; j < 8; j++) s += bins[threadIdx.x * 8 + j];
        g_sums[((size_t)b * NS + threadIdx.x) * 512 + c] = s;
    }
}

// ---------------------------------------------------------------------------
__global__ void k_final(float* __restrict__ out) {
    int idx = blockIdx.x * 256 + threadIdx.x;
    if (idx >= NB * NS * 512) return;
    int bs = idx >> 9;
    int cnt = g_cnt[bs];
    out[idx] = cnt > 0 ? g_sums[idx] / (float)cnt : 0.f;
}

// ---------------------------------------------------------------------------
extern "C" void kernel_launch(void* const* d_in, const int* in_sizes, int n_in,
                              void* d_out, int out_size) {
    const float* input  = (const float*)d_in[0];
    const float* segmap = (const float*)d_in[1];
    const float* w1 = (const float*)d_in[2];
    const float* b1 = (const float*)d_in[3];
    const float* w2 = (const float*)d_in[4];
    const float* b2 = (const float*)d_in[5];
    const float* w3 = (const float*)d_in[6];
    const float* b3 = (const float*)d_in[7];
    const float* w4 = (const float*)d_in[8];
    const float* b4 = (const float*)d_in[9];
    const float* w5 = (const float*)d_in[10];
    const float* b5 = (const float*)d_in[11];
    float* out = (float*)d_out;

    float* act1;  cudaGetSymbolAddress((void**)&act1, g_act1);
    float* act2;  cudaGetSymbolAddress((void**)&act2, g_act2);
    float* act3;  cudaGetSymbolAddress((void**)&act3, g_act3);
    float* act4;  cudaGetSymbolAddress((void**)&act4, g_act4);
    float* codes; cudaGetSymbolAddress((void**)&codes, g_codes);

    k_zero_cnt<<<1, 256>>>();

    // L1
    k_conv1<<<dim3(256, NB * 32), 256>>>(input, w1, b1);
    k_in_lrelu<<<NB * 32, 256>>>(act1, 65536);
    // L2: 32->64 @128x128 out
    k_conv_s2_mma<32, 256><<<dim3(128, NB, 1), 128>>>(act1, w2, b2, act2, 64);
    k_in_lrelu<<<NB * 64, 256>>>(act2, 16384);
    // L3: 64->128 @64x64 out
    k_conv_s2_mma<64, 128><<<dim3(32, NB, 2), 128>>>(act2, w3, b3, act3, 128);
    k_in_lrelu<<<NB * 128, 256>>>(act3, 4096);
    // L4 (transposed conv, tf32 mma)
    k_convT_mma<<<dim3(32, NB, 16), 128>>>(act3, w4, b4, act4);
    k_in_lrelu<<<NB * 256, 256>>>(act4, 16384);
    // L5 (+tanh, tf32 mma, proven tiling)
    k_conv5_mma<<<dim3(128, NB, 8), 128>>>(act4, w5, b5, codes);
    // pooling
    k_label<<<dim3(64, NB), 256>>>(segmap);
    k_pool<<<NB * 512, 256>>>(codes);
    k_final<<<(NB * NS * 512 + 255) / 256, 256>>>(out);
}

// round 6
// speedup vs baseline: 1.2498x; 1.0984x over previous
#include <cuda_runtime.h>
#include <cuda_bf16.h>
#include <math.h>

// ---------------------------------------------------------------------------
// B=8; input [8,3,256,256]; segmap [8,19,256,256]
// L1: reflect-pad conv 3->32, 256x256, IN, lrelu       (scalar)
// L2: conv s2 p1 32->64, 128x128, IN, lrelu            (tf32 mma)
// L3: conv s2 p1 64->128, 64x64, IN, lrelu             (tf32 mma)
// L4: convT s2 p1 op1 128->256, 128x128, IN, lrelu     (tf32 mma per parity class)
// L5: reflect-pad conv 256->512, 128x128, tanh         (tf32 mma, cog-fastest grid)
// pool: nearest one-hot segmap -> region means -> out [8,19,512]
// ---------------------------------------------------------------------------

#define NB 8
#define NS 19

__device__ float g_act1[NB * 32 * 256 * 256];
__device__ float g_act2[NB * 64 * 128 * 128];
__device__ float g_act3[NB * 128 * 64 * 64];
__device__ float g_act4[NB * 256 * 128 * 128];
__device__ float g_codes[(size_t)NB * 512 * 128 * 128];
__device__ int   g_label[NB * 128 * 128];
__device__ float g_sums[NB * NS * 512];
__device__ int   g_cnt[NB * NS];

__device__ __forceinline__ int refl(int v, int n) {
    return v < 0 ? -v : (v >= n ? 2 * n - 2 - v : v);
}

__device__ __forceinline__ unsigned f2tf(float f) {
    unsigned u;
    asm("cvt.rna.tf32.f32 %0, %1;" : "=r"(u) : "f"(f));
    return u;
}

__device__ __forceinline__ void mma_tf32(float* c, const unsigned* a, const unsigned* b) {
    asm volatile(
        "mma.sync.aligned.m16n8k8.row.col.f32.tf32.tf32.f32 "
        "{%0,%1,%2,%3}, {%4,%5,%6,%7}, {%8,%9}, {%0,%1,%2,%3};"
        : "+f"(c[0]), "+f"(c[1]), "+f"(c[2]), "+f"(c[3])
        : "r"(a[0]), "r"(a[1]), "r"(a[2]), "r"(a[3]), "r"(b[0]), "r"(b[1]));
}

// ---------------------------------------------------------------------------
__global__ void k_zero_cnt() {
    int i = threadIdx.x;
    if (i < NB * NS) g_cnt[i] = 0;
}

// ---------------------------------------------------------------------------
// conv1: reflect pad, 3->32, 256x256 (scalar; tiny)
// ---------------------------------------------------------------------------
__global__ void k_conv1(const float* __restrict__ in, const float* __restrict__ w,
                        const float* __restrict__ bias) {
    int p = blockIdx.y;
    int b = p >> 5, co = p & 31;
    __shared__ float ws[27];
    __shared__ float bs;
    if (threadIdx.x < 27) ws[threadIdx.x] = w[co * 27 + threadIdx.x];
    if (threadIdx.x == 0) bs = bias[co];
    __syncthreads();
    int idx = blockIdx.x * 256 + threadIdx.x;
    int y = idx >> 8, x = idx & 255;
    int ry[3], rx[3];
#pragma unroll
    for (int k = 0; k < 3; k++) { ry[k] = refl(y - 1 + k, 256); rx[k] = refl(x - 1 + k, 256); }
    float acc = bs;
#pragma unroll
    for (int ci = 0; ci < 3; ci++) {
        const float* ip = in + ((size_t)(b * 3 + ci)) * 65536;
#pragma unroll
        for (int ky = 0; ky < 3; ky++) {
            const float* row = ip + ry[ky] * 256;
#pragma unroll
            for (int kx = 0; kx < 3; kx++)
                acc = fmaf(row[rx[kx]], ws[ci * 9 + ky * 3 + kx], acc);
        }
    }
    g_act1[(size_t)p * 65536 + idx] = acc;
}

// ---------------------------------------------------------------------------
// fused instance-norm + leaky relu (in place)
// ---------------------------------------------------------------------------
__global__ void k_in_lrelu(float* __restrict__ buf, int HW) {
    float* p = buf + (size_t)blockIdx.x * HW;
    float s = 0.f, s2 = 0.f;
    for (int i = threadIdx.x; i < HW; i += 256) {
        float v = p[i];
        s += v;
        s2 = fmaf(v, v, s2);
    }
#pragma unroll
    for (int o = 16; o; o >>= 1) {
        s  += __shfl_down_sync(0xffffffffu, s, o);
        s2 += __shfl_down_sync(0xffffffffu, s2, o);
    }
    __shared__ float sh[16];
    __shared__ float mr[2];
    int wid = threadIdx.x >> 5, lid = threadIdx.x & 31;
    if (lid == 0) { sh[wid] = s; sh[8 + wid] = s2; }
    __syncthreads();
    if (threadIdx.x == 0) {
        float ts = 0.f, t2 = 0.f;
        for (int j = 0; j < 8; j++) { ts += sh[j]; t2 += sh[8 + j]; }
        float inv = 1.0f / (float)HW;
        float m = ts * inv;
        float var = t2 * inv - m * m;
        mr[0] = m;
        mr[1] = rsqrtf(var + 1e-5f);
    }
    __syncthreads();
    float m = mr[0], r = mr[1];
    for (int i = threadIdx.x; i < HW; i += 256) {
        float v = (p[i] - m) * r;
        p[i] = v > 0.f ? v : 0.2f * v;
    }
}

// ---------------------------------------------------------------------------
// stride-2 conv via tf32 mma (k=3, p=1). 64 cout x 128 out-pixels per block.
// grid: (COUT/64, tiles, NB) — cog fastest for L2 locality.
// ---------------------------------------------------------------------------
template <int CIN, int HIN>
__global__ __launch_bounds__(128) void k_conv_s2_mma(const float* __restrict__ in,
                                                     const float* __restrict__ w,
                                                     const float* __restrict__ bias,
                                                     float* __restrict__ out,
                                                     int cout_total) {
    constexpr int HOUT = HIN / 2;
    constexpr int XTILES = HOUT / 16;
    const int b = blockIdx.z;
    const int cog = blockIdx.x;
    const int y0 = (blockIdx.y / XTILES) * 8;
    const int x0 = (blockIdx.y % XTILES) * 16;

    const int tid = threadIdx.x;
    const int lane = tid & 31;
    const int ww = tid >> 5;
    const int mwarp = ww & 1;
    const int nwarp = ww >> 1;
    const int gid = lane >> 2;
    const int tig = lane & 3;

    __shared__ unsigned s_in[8 * 569];
    __shared__ unsigned s_w[64 * 72];

    float acc[2][8][4];
#pragma unroll
    for (int mt = 0; mt < 2; mt++)
#pragma unroll
        for (int j = 0; j < 8; j++)
#pragma unroll
            for (int q = 0; q < 4; q++) acc[mt][j][q] = 0.f;

    const float* inb = in + (size_t)b * CIN * HIN * HIN;
    const float* wb = w + (size_t)cog * 64 * CIN * 9;
    const int iy0 = 2 * y0 - 1, ix0 = 2 * x0 - 1;

    for (int cc = 0; cc < CIN / 8; cc++) {
        __syncthreads();
        for (int idx = tid; idx < 8 * 561; idx += 128) {
            int c = idx / 561, r = idx - c * 561;
            int rr = r / 33, cx = r - rr * 33;
            int gy = iy0 + rr, gx = ix0 + cx;
            float v = ((unsigned)gy < (unsigned)HIN && (unsigned)gx < (unsigned)HIN)
                          ? inb[((size_t)(cc * 8 + c) * HIN + gy) * HIN + gx]
                          : 0.f;
            s_in[c * 569 + rr * 33 + cx] = f2tf(v);
        }
        for (int idx = tid; idx < 64 * 72; idx += 128) {
            int co = idx / 72, kk = idx - co * 72;
            s_w[co * 72 + kk] = f2tf(wb[(size_t)co * CIN * 9 + cc * 72 + kk]);
        }
        __syncthreads();

#pragma unroll
        for (int t = 0; t < 9; t++) {
            const int ky = t / 3, kx = t - ky * 3;
            unsigned a[2][4];
#pragma unroll
            for (int mt = 0; mt < 2; mt++) {
                int mrow = mwarp * 32 + mt * 16 + gid;
                a[mt][0] = s_w[mrow * 72 + tig * 9 + t];
                a[mt][1] = s_w[(mrow + 8) * 72 + tig * 9 + t];
                a[mt][2] = s_w[mrow * 72 + (tig + 4) * 9 + t];
                a[mt][3] = s_w[(mrow + 8) * 72 + (tig + 4) * 9 + t];
            }
#pragma unroll
            for (int j = 0; j < 8; j++) {
                int jj = nwarp * 8 + j;
                int row = jj >> 1;
                int xcol = (jj & 1) * 8;
                int hy = 2 * row + ky;
                int hx = 2 * (xcol + gid) + kx;
                unsigned bf[2];
                bf[0] = s_in[tig * 569 + hy * 33 + hx];
                bf[1] = s_in[(tig + 4) * 569 + hy * 33 + hx];
                mma_tf32(acc[0][j], a[0], bf);
                mma_tf32(acc[1][j], a[1], bf);
            }
        }
    }

#pragma unroll
    for (int mt = 0; mt < 2; mt++) {
        int co0 = cog * 64 + mwarp * 32 + mt * 16 + gid;
        float bs0 = bias[co0];
        float bs1 = bias[co0 + 8];
#pragma unroll
        for (int j = 0; j < 8; j++) {
            int jj = nwarp * 8 + j;
            int y = y0 + (jj >> 1);
            int x = x0 + (jj & 1) * 8 + 2 * tig;
            float2 v0 = make_float2(acc[mt][j][0] + bs0, acc[mt][j][1] + bs0);
            float2 v1 = make_float2(acc[mt][j][2] + bs1, acc[mt][j][3] + bs1);
            *(float2*)&out[(((size_t)(b * cout_total + co0)) * HOUT + y) * HOUT + x] = v0;
            *(float2*)&out[(((size_t)(b * cout_total + co0 + 8)) * HOUT + y) * HOUT + x] = v1;
        }
    }
}

// ---------------------------------------------------------------------------
// convT via tf32 mma: [B,128,64,64] -> [B,256,128,128], per parity class.
// grid: (cog*cls=16, tiles=32, NB) — channel/class fastest for L2 locality.
// ---------------------------------------------------------------------------
__global__ __launch_bounds__(128) void k_convT_mma(const float* __restrict__ in,
                                                   const float* __restrict__ w,
                                                   const float* __restrict__ bias,
                                                   float* __restrict__ out) {
    const int b = blockIdx.z;
    const int z = blockIdx.x;
    const int cog = z >> 2, cls = z & 3;
    const int py = cls >> 1, px = cls & 1;
    const int y0 = (blockIdx.y >> 2) * 8;
    const int x0 = (blockIdx.y & 3) * 16;

    const int tid = threadIdx.x;
    const int lane = tid & 31;
    const int ww = tid >> 5;
    const int mwarp = ww & 1;
    const int nwarp = ww >> 1;
    const int gid = lane >> 2;
    const int tig = lane & 3;

    int nky = py ? 2 : 1, nkx = px ? 2 : 1;
    int kyA[2] = {1, 0}, dyA[2] = {0, 0};
    if (py) { kyA[0] = 0; dyA[0] = 1; kyA[1] = 2; dyA[1] = 0; }
    int kxA[2] = {1, 0}, dxA[2] = {0, 0};
    if (px) { kxA[0] = 0; dxA[0] = 1; kxA[1] = 2; dxA[1] = 0; }
    const int ntaps = nky * nkx;
    int tval[4], tdy[4], tdx[4];
    for (int a = 0; a < nky; a++)
        for (int e = 0; e < nkx; e++) {
            int ta = a * nkx + e;
            tval[ta] = kyA[a] * 3 + kxA[e];
            tdy[ta] = dyA[a];
            tdx[ta] = dxA[e];
        }

    __shared__ unsigned s_in[8 * 168];
    __shared__ unsigned s_w[4 * 64 * 12];

    float acc[2][8][4];
#pragma unroll
    for (int mt = 0; mt < 2; mt++)
#pragma unroll
        for (int j = 0; j < 8; j++)
#pragma unroll
            for (int q = 0; q < 4; q++) acc[mt][j][q] = 0.f;

    const float* inb = in + (size_t)b * 128 * 4096;

    for (int cc = 0; cc < 16; cc++) {
        __syncthreads();
        for (int idx = tid; idx < 8 * 153; idx += 128) {
            int c = idx / 153, r = idx - c * 153;
            int rr = r / 17, cx = r - rr * 17;
            int gy = y0 + rr, gx = x0 + cx;
            float v = (gy < 64 && gx < 64)
                          ? inb[((size_t)(cc * 8 + c) * 64 + gy) * 64 + gx]
                          : 0.f;
            s_in[c * 168 + rr * 17 + cx] = f2tf(v);
        }
        for (int idx = tid; idx < ntaps * 512; idx += 128) {
            int ta = idx >> 9;
            int rem = idx & 511;
            int co = rem >> 3, q = rem & 7;
            float v = w[(((size_t)(cc * 8 + q)) * 256 + cog * 64 + co) * 9 + tval[ta]];
            s_w[(ta * 64 + co) * 12 + q] = f2tf(v);
        }
        __syncthreads();

        for (int ta = 0; ta < ntaps; ta++) {
            unsigned a[2][4];
#pragma unroll
            for (int mt = 0; mt < 2; mt++) {
                int mrow = mwarp * 32 + mt * 16 + gid;
                a[mt][0] = s_w[(ta * 64 + mrow) * 12 + tig];
                a[mt][1] = s_w[(ta * 64 + mrow + 8) * 12 + tig];
                a[mt][2] = s_w[(ta * 64 + mrow) * 12 + tig + 4];
                a[mt][3] = s_w[(ta * 64 + mrow + 8) * 12 + tig + 4];
            }
            int dy = tdy[ta], dx = tdx[ta];
#pragma unroll
            for (int j = 0; j < 8; j++) {
                int jj = nwarp * 8 + j;
                int hy = (jj >> 1) + dy;
                int hx = (jj & 1) * 8 + gid + dx;
                unsigned bf[2];
                bf[0] = s_in[tig * 168 + hy * 17 + hx];
                bf[1] = s_in[(tig + 4) * 168 + hy * 17 + hx];
                mma_tf32(acc[0][j], a[0], bf);
                mma_tf32(acc[1][j], a[1], bf);
            }
        }
    }

#pragma unroll
    for (int mt = 0; mt < 2; mt++) {
        int co0 = cog * 64 + mwarp * 32 + mt * 16 + gid;
        float bs0 = bias[co0];
        float bs1 = bias[co0 + 8];
#pragma unroll
        for (int j = 0; j < 8; j++) {
            int jj = nwarp * 8 + j;
            int yc = y0 + (jj >> 1);
            int xc = x0 + (jj & 1) * 8 + 2 * tig;
            int y = 2 * yc + py;
            int x = 2 * xc + px;
            size_t o0 = (((size_t)(b * 256 + co0)) * 128 + y) * 128 + x;
            size_t o1 = (((size_t)(b * 256 + co0 + 8)) * 128 + y) * 128 + x;
            out[o0] = acc[mt][j][0] + bs0;
            out[o0 + 2] = acc[mt][j][1] + bs0;
            out[o1] = acc[mt][j][2] + bs1;
            out[o1 + 2] = acc[mt][j][3] + bs1;
        }
    }
}

// ---------------------------------------------------------------------------
// conv5 via tf32 mma: 64 cout x 128 px (8x16), grid (cog=8, tile=128, b=NB).
// cog fastest-varying -> all 8 cout groups of one tile are co-resident, so the
// act4 halo is fetched from DRAM once and served 7x from L2.
// ---------------------------------------------------------------------------
__global__ __launch_bounds__(128) void k_conv5_mma(const float* __restrict__ in,
                                                   const float* __restrict__ w,
                                                   const float* __restrict__ bias,
                                                   float* __restrict__ out) {
    const int b = blockIdx.z;
    const int cog = blockIdx.x;
    const int y0 = (blockIdx.y >> 3) * 8;
    const int x0 = (blockIdx.y & 7) * 16;

    const int tid = threadIdx.x;
    const int lane = tid & 31;
    const int ww = tid >> 5;
    const int mwarp = ww & 1;
    const int nwarp = ww >> 1;
    const int gid = lane >> 2;
    const int tig = lane & 3;

    __shared__ unsigned s_in[8 * 184];
    __shared__ unsigned s_w[64 * 72];

    float acc[2][8][4];
#pragma unroll
    for (int mt = 0; mt < 2; mt++)
#pragma unroll
        for (int j = 0; j < 8; j++)
#pragma unroll
            for (int q = 0; q < 4; q++) acc[mt][j][q] = 0.f;

    const float* inb = in + (size_t)b * 256 * 16384;
    const float* wb = w + (size_t)cog * 64 * 2304;

    for (int cc = 0; cc < 32; cc++) {
        __syncthreads();
        for (int idx = tid; idx < 8 * 180; idx += 128) {
            int c = idx / 180, r = idx - c * 180;
            int yy = r / 18, xx = r - yy * 18;
            int gy = refl(y0 - 1 + yy, 128);
            int gx = refl(x0 - 1 + xx, 128);
            s_in[c * 184 + yy * 18 + xx] =
                f2tf(inb[((size_t)(cc * 8 + c) * 128 + gy) * 128 + gx]);
        }
        for (int idx = tid; idx < 64 * 72; idx += 128) {
            int co = idx / 72, kk = idx - co * 72;
            s_w[co * 72 + kk] = f2tf(wb[(size_t)co * 2304 + cc * 72 + kk]);
        }
        __syncthreads();

#pragma unroll
        for (int t = 0; t < 9; t++) {
            const int ky = t / 3, kx = t - ky * 3;
            unsigned a[2][4];
#pragma unroll
            for (int mt = 0; mt < 2; mt++) {
                int mrow = mwarp * 32 + mt * 16 + gid;
                a[mt][0] = s_w[mrow * 72 + tig * 9 + t];
                a[mt][1] = s_w[(mrow + 8) * 72 + tig * 9 + t];
                a[mt][2] = s_w[mrow * 72 + (tig + 4) * 9 + t];
                a[mt][3] = s_w[(mrow + 8) * 72 + (tig + 4) * 9 + t];
            }
            unsigned bcur[2], bnxt[2];
            {
                int jj = nwarp * 8;
                int hy = (jj >> 1) + ky;
                int hx = (jj & 1) * 8 + gid + kx;
                bcur[0] = s_in[tig * 184 + hy * 18 + hx];
                bcur[1] = s_in[(tig + 4) * 184 + hy * 18 + hx];
            }
#pragma unroll
            for (int j = 0; j < 8; j++) {
                if (j < 7) {
                    int jj = nwarp * 8 + j + 1;
                    int hy = (jj >> 1) + ky;
                    int hx = (jj & 1) * 8 + gid + kx;
                    bnxt[0] = s_in[tig * 184 + hy * 18 + hx];
                    bnxt[1] = s_in[(tig + 4) * 184 + hy * 18 + hx];
                }
                mma_tf32(acc[0][j], a[0], bcur);
                mma_tf32(acc[1][j], a[1], bcur);
                bcur[0] = bnxt[0];
                bcur[1] = bnxt[1];
            }
        }
    }

    const int coutA = cog * 64 + mwarp * 32;
#pragma unroll
    for (int mt = 0; mt < 2; mt++) {
        int co0 = coutA + mt * 16 + gid;
        float bs0 = bias[co0];
        float bs1 = bias[co0 + 8];
#pragma unroll
        for (int j = 0; j < 8; j++) {
            int jj = nwarp * 8 + j;
            int y = y0 + (jj >> 1);
            int x = x0 + (jj & 1) * 8 + 2 * tig;
            float2 v0 = make_float2(tanhf(acc[mt][j][0] + bs0), tanhf(acc[mt][j][1] + bs0));
            float2 v1 = make_float2(tanhf(acc[mt][j][2] + bs1), tanhf(acc[mt][j][3] + bs1));
            *(float2*)&out[(((size_t)(b * 512 + co0)) * 128 + y) * 128 + x] = v0;
            *(float2*)&out[(((size_t)(b * 512 + co0 + 8)) * 128 + y) * 128 + x] = v1;
        }
    }
}

// ---------------------------------------------------------------------------
// labels + counts (nearest 256->128 = (2h,2w))
// ---------------------------------------------------------------------------
__global__ void k_label(const float* __restrict__ seg) {
    int b = blockIdx.y;
    int i = blockIdx.x * 256 + threadIdx.x;
    int h = i >> 7, wv = i & 127;
    const float* sp = seg + (size_t)b * NS * 65536 + (2 * h) * 256 + 2 * wv;
    int lab = 0;
#pragma unroll 1
    for (int s = 0; s < NS; s++) {
        float v = sp[(size_t)s * 65536];
        if (v > 0.f) lab = s;
    }
    g_label[b * 16384 + i] = lab;
    atomicAdd(&g_cnt[b * NS + lab], 1);
}

// ---------------------------------------------------------------------------
// segment-sum pooling, vectorized
// ---------------------------------------------------------------------------
__global__ void k_pool(const float* __restrict__ codes) {
    int c = blockIdx.x & 511;
    int b = blockIdx.x >> 9;
    __shared__ float bins[NS * 8];
    if (threadIdx.x < NS * 8) bins[threadIdx.x] = 0.f;
    __syncthreads();
    const float4* cp = (const float4*)(codes + ((size_t)(b * 512 + c)) * 16384);
    const int4* lp = (const int4*)(g_label + b * 16384);
    int sub = threadIdx.x & 7;
    for (int i = threadIdx.x; i < 4096; i += 256) {
        float4 v = cp[i];
        int4 l = lp[i];
        atomicAdd(&bins[l.x * 8 + sub], v.x);
        atomicAdd(&bins[l.y * 8 + sub], v.y);
        atomicAdd(&bins[l.z * 8 + sub], v.z);
        atomicAdd(&bins[l.w * 8 + sub], v.w);
    }
    __syncthreads();
    if (threadIdx.x < NS) {
        float s = 0.f;
#pragma unroll
        for (int j = 0; j < 8; j++) s += bins[threadIdx.x * 8 + j];
        g_sums[((size_t)b * NS + threadIdx.x) * 512 + c] = s;
    }
}

// ---------------------------------------------------------------------------
__global__ void k_final(float* __restrict__ out) {
    int idx = blockIdx.x * 256 + threadIdx.x;
    if (idx >= NB * NS * 512) return;
    int bs = idx >> 9;
    int cnt = g_cnt[bs];
    out[idx] = cnt > 0 ? g_sums[idx] / (float)cnt : 0.f;
}

// ---------------------------------------------------------------------------
extern "C" void kernel_launch(void* const* d_in, const int* in_sizes, int n_in,
                              void* d_out, int out_size) {
    const float* input  = (const float*)d_in[0];
    const float* segmap = (const float*)d_in[1];
    const float* w1 = (const float*)d_in[2];
    const float* b1 = (const float*)d_in[3];
    const float* w2 = (const float*)d_in[4];
    const float* b2 = (const float*)d_in[5];
    const float* w3 = (const float*)d_in[6];
    const float* b3 = (const float*)d_in[7];
    const float* w4 = (const float*)d_in[8];
    const float* b4 = (const float*)d_in[9];
    const float* w5 = (const float*)d_in[10];
    const float* b5 = (const float*)d_in[11];
    float* out = (float*)d_out;

    float* act1;  cudaGetSymbolAddress((void**)&act1, g_act1);
    float* act2;  cudaGetSymbolAddress((void**)&act2, g_act2);
    float* act3;  cudaGetSymbolAddress((void**)&act3, g_act3);
    float* act4;  cudaGetSymbolAddress((void**)&act4, g_act4);
    float* codes; cudaGetSymbolAddress((void**)&codes, g_codes);

    k_zero_cnt<<<1, 256>>>();

    // L1
    k_conv1<<<dim3(256, NB * 32), 256>>>(input, w1, b1);
    k_in_lrelu<<<NB * 32, 256>>>(act1, 65536);
    // L2: 32->64 @128x128 out
    k_conv_s2_mma<32, 256><<<dim3(1, 128, NB), 128>>>(act1, w2, b2, act2, 64);
    k_in_lrelu<<<NB * 64, 256>>>(act2, 16384);
    // L3: 64->128 @64x64 out
    k_conv_s2_mma<64, 128><<<dim3(2, 32, NB), 128>>>(act2, w3, b3, act3, 128);
    k_in_lrelu<<<NB * 128, 256>>>(act3, 4096);
    // L4 (transposed conv, tf32 mma; cog/cls fastest)
    k_convT_mma<<<dim3(16, 32, NB), 128>>>(act3, w4, b4, act4);
    k_in_lrelu<<<NB * 256, 256>>>(act4, 16384);
    // L5 (+tanh, tf32 mma; cog fastest for L2 reuse of act4)
    k_conv5_mma<<<dim3(8, 128, NB), 128>>>(act4, w5, b5, codes);
    // pooling
    k_label<<<dim3(64, NB), 256>>>(segmap);
    k_pool<<<NB * 512, 256>>>(codes);
    k_final<<<(NB * NS * 512 + 255) / 256, 256>>>(out);
}